// round 3
// baseline (speedup 1.0000x reference)
#include <cuda_runtime.h>

// Problem constants
#define HH   8
#define MSA  64
#define LL   256
#define DHD  64
#define DD   512
#define HMN  (HH*MSA)      // 512
#define NROWS (MSA*LL)     // 16384
#define NG   16            // m-groups
#define MPG  4             // m per group (NG*MPG = MSA)

// ---------------- device scratch (allocation-free rule: __device__ globals) -------------
__device__ float g_q[HMN*LL*DHD];            // [h*64+m][l][dh]   8.39M floats
__device__ float g_k[HMN*LL*DHD];
__device__ float g_v[HMN*LL*DHD];
__device__ float g_e2[(size_t)HMN*LL*LL];    // [hm][i][j]        33.5M floats
__device__ float g_zpart[NG*HH*LL*DHD];      // [g][h][i][d]
__device__ float g_apart[(size_t)NG*HH*LL*LL]; // [g][h][i][j]

// ================= Projection: C(16384x512) = X(16384x512) @ W^T(512x512) ==============
// 128x128 tile, BK=8, 256 threads, 8x8 micro. Output scattered into (h,m,l,dh) layout.
__global__ void proj_kernel(const float* __restrict__ x,
                            const float* __restrict__ Wq,
                            const float* __restrict__ Wk,
                            const float* __restrict__ Wv) {
    __shared__ float As[8*128];
    __shared__ float Bs[8*128];
    const float* W;
    float* out;
    if (blockIdx.z == 0)      { W = Wq; out = g_q; }
    else if (blockIdx.z == 1) { W = Wk; out = g_k; }
    else                      { W = Wv; out = g_v; }

    const int row0 = blockIdx.y * 128;
    const int col0 = blockIdx.x * 128;
    const int tid  = threadIdx.x;
    const int tx = tid & 15, ty = tid >> 4;
    const int lr = tid >> 1;            // 0..127
    const int lc = (tid & 1) * 4;       // 0 or 4

    float acc[8][8];
#pragma unroll
    for (int i = 0; i < 8; i++)
#pragma unroll
        for (int j = 0; j < 8; j++) acc[i][j] = 0.f;

    for (int k0 = 0; k0 < DD; k0 += 8) {
        float4 va = *(const float4*)(x + (size_t)(row0 + lr) * DD + k0 + lc);
        float4 vb = *(const float4*)(W + (size_t)(col0 + lr) * DD + k0 + lc);
        __syncthreads();
        As[(lc+0)*128 + lr] = va.x; As[(lc+1)*128 + lr] = va.y;
        As[(lc+2)*128 + lr] = va.z; As[(lc+3)*128 + lr] = va.w;
        Bs[(lc+0)*128 + lr] = vb.x; Bs[(lc+1)*128 + lr] = vb.y;
        Bs[(lc+2)*128 + lr] = vb.z; Bs[(lc+3)*128 + lr] = vb.w;
        __syncthreads();
#pragma unroll
        for (int k = 0; k < 8; k++) {
            float a[8], b[8];
#pragma unroll
            for (int ii = 0; ii < 8; ii++) a[ii] = As[k*128 + ty + 16*ii];
#pragma unroll
            for (int jj = 0; jj < 8; jj++) b[jj] = Bs[k*128 + tx + 16*jj];
#pragma unroll
            for (int ii = 0; ii < 8; ii++)
#pragma unroll
                for (int jj = 0; jj < 8; jj++) acc[ii][jj] += a[ii]*b[jj];
        }
    }
    // epilogue: row r = m*L + l, col c = h*64 + dh -> out[((h*64+m)*256+l)*64+dh]
#pragma unroll
    for (int ii = 0; ii < 8; ii++) {
#pragma unroll
        for (int jj = 0; jj < 8; jj++) {
            int r = row0 + ty + 16*ii;
            int c = col0 + tx + 16*jj;
            int hq = c >> 6, dh = c & 63, ms = r >> 8, l = r & 255;
            out[(((size_t)(hq*MSA + ms))*LL + l)*DHD + dh] = acc[ii][jj];
        }
    }
}

// ================= E2 precompute: per i, E2_i(512x256) = Qi(512x64) @ aK[i]^T ===========
// 128x128 tile, BK=8, same micro-kernel.  grid (jtiles=2, hmtiles=4, i=256)
__global__ void e2_kernel(const float* __restrict__ aK) {
    __shared__ float As[8*128];
    __shared__ float Bs[8*128];
    const int i   = blockIdx.z;
    const int hm0 = blockIdx.y * 128;
    const int j0  = blockIdx.x * 128;
    const int tid = threadIdx.x;
    const int tx = tid & 15, ty = tid >> 4;
    const int lr = tid >> 1;
    const int lc = (tid & 1) * 4;

    float acc[8][8];
#pragma unroll
    for (int a = 0; a < 8; a++)
#pragma unroll
        for (int b = 0; b < 8; b++) acc[a][b] = 0.f;

    for (int k0 = 0; k0 < DHD; k0 += 8) {
        // A row m_ = hm; element = g_q[(hm)*L*DH + i*64 + k]
        float4 va = *(const float4*)(g_q + (size_t)(hm0 + lr)*(LL*DHD) + (size_t)i*DHD + k0 + lc);
        float4 vb = *(const float4*)(aK + ((size_t)i*LL + j0 + lr)*DHD + k0 + lc);
        __syncthreads();
        As[(lc+0)*128 + lr] = va.x; As[(lc+1)*128 + lr] = va.y;
        As[(lc+2)*128 + lr] = va.z; As[(lc+3)*128 + lr] = va.w;
        Bs[(lc+0)*128 + lr] = vb.x; Bs[(lc+1)*128 + lr] = vb.y;
        Bs[(lc+2)*128 + lr] = vb.z; Bs[(lc+3)*128 + lr] = vb.w;
        __syncthreads();
#pragma unroll
        for (int k = 0; k < 8; k++) {
            float a[8], b[8];
#pragma unroll
            for (int ii = 0; ii < 8; ii++) a[ii] = As[k*128 + ty + 16*ii];
#pragma unroll
            for (int jj = 0; jj < 8; jj++) b[jj] = Bs[k*128 + tx + 16*jj];
#pragma unroll
            for (int ii = 0; ii < 8; ii++)
#pragma unroll
                for (int jj = 0; jj < 8; jj++) acc[ii][jj] += a[ii]*b[jj];
        }
    }
#pragma unroll
    for (int ii = 0; ii < 8; ii++) {
#pragma unroll
        for (int jj = 0; jj < 8; jj++) {
            int hm = hm0 + ty + 16*ii;
            int j  = j0 + tx + 16*jj;
            g_e2[((size_t)hm*LL + i)*LL + j] = acc[ii][jj];
        }
    }
}

// ================= Fused attention ======================================================
// grid (itile=4, h=8, g=16); 256 threads; loops mm=0..3 (m = g*4+mm).
// Per m: S(64x256) = (q@k^T + E2)/8 -> softmax -> zacc += S@v ; Aacc += S.
// Writes g_zpart[g][h][itile] and g_apart[g][h][itile].
__global__ void attn_kernel() {
    extern __shared__ float sm[];
    float* qs   = sm;                         // 64x65  (transposed [d][i], pad 65)
    float* kb   = sm + 64*65;                 // 64x129 ([d][j] pad) / reused as vs 128x64
    float* S    = sm + 64*65 + 64*129;        // 64x257 ([i][j] pad 257)
    float* Aacc = S + 64*257;                 // 64x256

    const int i0  = blockIdx.x * 64;
    const int h   = blockIdx.y;
    const int g   = blockIdx.z;
    const int tid = threadIdx.x;
    const int tx = tid & 15, ty = tid >> 4;
    const int lane = tid & 31, w = tid >> 5;

    float zacc[4][4];
#pragma unroll
    for (int a = 0; a < 4; a++)
#pragma unroll
        for (int b = 0; b < 4; b++) zacc[a][b] = 0.f;

    for (int e = tid; e < 64*256; e += 256) Aacc[e] = 0.f;

    for (int mm = 0; mm < MPG; mm++) {
        const int m  = g*MPG + mm;
        const int hm = h*MSA + m;
        const float* qg = g_q + (size_t)hm*LL*DHD;
        const float* kg = g_k + (size_t)hm*LL*DHD;
        const float* vg = g_v + (size_t)hm*LL*DHD;
        const float* e2p = g_e2 + ((size_t)hm*LL + i0)*LL;

        __syncthreads();
        // load q tile transposed: qs[d][il]
        for (int e = tid; e < 64*64; e += 256) {
            int il = e >> 6, d = e & 63;
            qs[d*65 + il] = qg[(size_t)(i0 + il)*DHD + d];
        }
        // ---- S = (q k^T + E2)/8, two 128-col chunks, 4x8 micro ----
        for (int jc = 0; jc < 2; jc++) {
            __syncthreads();
            for (int e = tid; e < 128*64; e += 256) {
                int jl = e >> 6, d = e & 63;
                kb[d*129 + jl] = kg[(size_t)(jc*128 + jl)*DHD + d];
            }
            __syncthreads();
            float acc[4][8];
#pragma unroll
            for (int a = 0; a < 4; a++)
#pragma unroll
                for (int b = 0; b < 8; b++) acc[a][b] = 0.f;
#pragma unroll 16
            for (int d = 0; d < 64; d++) {
                float a[4], b[8];
#pragma unroll
                for (int ii = 0; ii < 4; ii++) a[ii] = qs[d*65 + ty + 16*ii];
#pragma unroll
                for (int jj = 0; jj < 8; jj++) b[jj] = kb[d*129 + tx + 16*jj];
#pragma unroll
                for (int ii = 0; ii < 4; ii++)
#pragma unroll
                    for (int jj = 0; jj < 8; jj++) acc[ii][jj] += a[ii]*b[jj];
            }
#pragma unroll
            for (int ii = 0; ii < 4; ii++) {
#pragma unroll
                for (int jj = 0; jj < 8; jj++) {
                    int il = ty + 16*ii;
                    int j  = jc*128 + tx + 16*jj;
                    S[il*257 + j] = (acc[ii][jj] + e2p[(size_t)il*LL + j]) * 0.125f;
                }
            }
        }
        __syncthreads();
        // ---- softmax: 8 warps, each handles rows w, w+8, ..., w+56 ----
        for (int rr = 0; rr < 8; rr++) {
            int r = w + 8*rr;
            float* Sr = S + r*257;
            float v[8];
            float mx = -1e30f;
#pragma unroll
            for (int c = 0; c < 8; c++) { v[c] = Sr[lane + 32*c]; mx = fmaxf(mx, v[c]); }
#pragma unroll
            for (int o = 16; o > 0; o >>= 1) mx = fmaxf(mx, __shfl_xor_sync(0xffffffffu, mx, o));
            float sum = 0.f;
#pragma unroll
            for (int c = 0; c < 8; c++) { v[c] = __expf(v[c] - mx); sum += v[c]; }
#pragma unroll
            for (int o = 16; o > 0; o >>= 1) sum += __shfl_xor_sync(0xffffffffu, sum, o);
            float inv = 1.f / sum;
#pragma unroll
            for (int c = 0; c < 8; c++) Sr[lane + 32*c] = v[c] * inv;
        }
        __syncthreads();
        // ---- Aacc += alpha ----
        for (int e = tid; e < 64*256; e += 256) {
            int il = e >> 8, j = e & 255;
            Aacc[e] += S[il*257 + j];
        }
        // ---- zacc += alpha @ v, two 128-j chunks, 4x4 micro ----
        for (int jc = 0; jc < 2; jc++) {
            __syncthreads();
            for (int e = tid; e < 128*64; e += 256)
                kb[e] = vg[(size_t)jc*128*DHD + e];       // vs[jl*64+d]
            __syncthreads();
#pragma unroll 8
            for (int jl = 0; jl < 128; jl++) {
                float a[4], b[4];
#pragma unroll
                for (int ii = 0; ii < 4; ii++) a[ii] = S[(ty + 16*ii)*257 + jc*128 + jl];
#pragma unroll
                for (int dd = 0; dd < 4; dd++) b[dd] = kb[jl*64 + tx + 16*dd];
#pragma unroll
                for (int ii = 0; ii < 4; ii++)
#pragma unroll
                    for (int dd = 0; dd < 4; dd++) zacc[ii][dd] += a[ii]*b[dd];
            }
        }
        __syncthreads();
    }
    // write partials
#pragma unroll
    for (int ii = 0; ii < 4; ii++)
#pragma unroll
        for (int dd = 0; dd < 4; dd++)
            g_zpart[(((size_t)g*HH + h)*LL + i0 + ty + 16*ii)*DHD + tx + 16*dd] = zacc[ii][dd];

    size_t abase = (((size_t)g*HH + h)*LL + i0)*LL;
    for (int e = tid; e < 64*256; e += 256) g_apart[abase + e] = Aacc[e];
}

// ================= Epilogue: reduce partials, z2 = A @ aV, write out =====================
// grid i = 256, 256 threads.
__global__ void final_kernel(const float* __restrict__ aV, float* __restrict__ out) {
    __shared__ float zs[512];      // [h*64+d]
    __shared__ float As[HH*LL];    // [h][j]
    const int i = blockIdx.x;
    const int tid = threadIdx.x;

    for (int p = tid; p < 512; p += 256) {
        int hq = p >> 6, d = p & 63;
        float s = 0.f;
#pragma unroll
        for (int g = 0; g < NG; g++)
            s += g_zpart[(((size_t)g*HH + hq)*LL + i)*DHD + d];
        zs[p] = s;
    }
    for (int p = tid; p < HH*LL; p += 256) {
        int hq = p >> 8, j = p & 255;
        float s = 0.f;
#pragma unroll
        for (int g = 0; g < NG; g++)
            s += g_apart[(((size_t)g*HH + hq)*LL + i)*LL + j];
        As[p] = s;
    }
    __syncthreads();

    const int d = tid & 63, hq2 = tid >> 6;   // hq2 in 0..3, handles heads 2*hq2, 2*hq2+1
    const float* av = aV + (size_t)i*LL*DHD;
    float a0 = 0.f, a1 = 0.f;
    for (int j = 0; j < LL; j++) {
        float vv = av[(size_t)j*DHD + d];
        a0 += As[(hq2*2 + 0)*LL + j] * vv;
        a1 += As[(hq2*2 + 1)*LL + j] * vv;
    }
    out[(size_t)i*DD + (hq2*2 + 0)*DHD + d] = zs[(hq2*2 + 0)*DHD + d] + a0;
    out[(size_t)i*DD + (hq2*2 + 1)*DHD + d] = zs[(hq2*2 + 1)*DHD + d] + a1;
}

// ================= launch ================================================================
extern "C" void kernel_launch(void* const* d_in, const int* in_sizes, int n_in,
                              void* d_out, int out_size) {
    const float* x  = (const float*)d_in[0];
    const float* Wq = (const float*)d_in[1];
    const float* Wk = (const float*)d_in[2];
    const float* Wv = (const float*)d_in[3];
    const float* aK = (const float*)d_in[4];
    const float* aV = (const float*)d_in[5];
    float* out = (float*)d_out;

    proj_kernel<<<dim3(4, 128, 3), 256>>>(x, Wq, Wk, Wv);
    e2_kernel<<<dim3(2, 4, 256), 256>>>(aK);

    const int attn_smem = (64*65 + 64*129 + 64*257 + 64*256) * (int)sizeof(float); // 180,992 B
    cudaFuncSetAttribute(attn_kernel, cudaFuncAttributeMaxDynamicSharedMemorySize, attn_smem);
    attn_kernel<<<dim3(4, 8, NG), 256, attn_smem>>>();

    final_kernel<<<256, 256>>>(aV, out);
}

// round 6
// speedup vs baseline: 1.0064x; 1.0064x over previous
#include <cuda_runtime.h>

// Problem constants
#define HH   8
#define MSA  64
#define LL   256
#define DHD  64
#define DD   512
#define HMN  (HH*MSA)      // 512
#define NROWS (MSA*LL)     // 16384
#define NG   16            // m-groups
#define MPG  4             // m per group (NG*MPG = MSA)

// ---------------- device scratch (allocation-free rule: __device__ globals) -------------
__device__ float g_q[HMN*LL*DHD];            // [h*64+m][l][dh]   8.39M floats
__device__ float g_k[HMN*LL*DHD];
__device__ float g_v[HMN*LL*DHD];
__device__ float g_e2[(size_t)HMN*LL*LL];    // [hm][i][j]        33.5M floats
__device__ float g_zpart[NG*HH*LL*DHD];      // [g][h][i][d]
__device__ float g_apart[(size_t)NG*HH*LL*LL]; // [g][h][i][j]

// ================= Projection: C(16384x512) = X(16384x512) @ W^T(512x512) ==============
// 128x128 tile, BK=8, 256 threads, 8x8 micro. Output scattered into (h,m,l,dh) layout.
__global__ void proj_kernel(const float* __restrict__ x,
                            const float* __restrict__ Wq,
                            const float* __restrict__ Wk,
                            const float* __restrict__ Wv) {
    __shared__ float As[8*128];
    __shared__ float Bs[8*128];
    const float* W;
    float* out;
    if (blockIdx.z == 0)      { W = Wq; out = g_q; }
    else if (blockIdx.z == 1) { W = Wk; out = g_k; }
    else                      { W = Wv; out = g_v; }

    const int row0 = blockIdx.y * 128;
    const int col0 = blockIdx.x * 128;
    const int tid  = threadIdx.x;
    const int tx = tid & 15, ty = tid >> 4;
    const int lr = tid >> 1;            // 0..127
    const int lc = (tid & 1) * 4;       // 0 or 4

    float acc[8][8];
#pragma unroll
    for (int i = 0; i < 8; i++)
#pragma unroll
        for (int j = 0; j < 8; j++) acc[i][j] = 0.f;

    for (int k0 = 0; k0 < DD; k0 += 8) {
        float4 va = *(const float4*)(x + (size_t)(row0 + lr) * DD + k0 + lc);
        float4 vb = *(const float4*)(W + (size_t)(col0 + lr) * DD + k0 + lc);
        __syncthreads();
        As[(lc+0)*128 + lr] = va.x; As[(lc+1)*128 + lr] = va.y;
        As[(lc+2)*128 + lr] = va.z; As[(lc+3)*128 + lr] = va.w;
        Bs[(lc+0)*128 + lr] = vb.x; Bs[(lc+1)*128 + lr] = vb.y;
        Bs[(lc+2)*128 + lr] = vb.z; Bs[(lc+3)*128 + lr] = vb.w;
        __syncthreads();
#pragma unroll
        for (int k = 0; k < 8; k++) {
            float a[8], b[8];
#pragma unroll
            for (int ii = 0; ii < 8; ii++) a[ii] = As[k*128 + ty + 16*ii];
#pragma unroll
            for (int jj = 0; jj < 8; jj++) b[jj] = Bs[k*128 + tx + 16*jj];
#pragma unroll
            for (int ii = 0; ii < 8; ii++)
#pragma unroll
                for (int jj = 0; jj < 8; jj++) acc[ii][jj] += a[ii]*b[jj];
        }
    }
    // epilogue: row r = m*L + l, col c = h*64 + dh -> out[((h*64+m)*256+l)*64+dh]
#pragma unroll
    for (int ii = 0; ii < 8; ii++) {
#pragma unroll
        for (int jj = 0; jj < 8; jj++) {
            int r = row0 + ty + 16*ii;
            int c = col0 + tx + 16*jj;
            int hq = c >> 6, dh = c & 63, ms = r >> 8, l = r & 255;
            out[(((size_t)(hq*MSA + ms))*LL + l)*DHD + dh] = acc[ii][jj];
        }
    }
}

// ================= E2 precompute: per i, E2_i(512x256) = Qi(512x64) @ aK[i]^T ===========
// 128x128 tile, BK=8, same micro-kernel.  grid (jtiles=2, hmtiles=4, i=256)
__global__ void e2_kernel(const float* __restrict__ aK) {
    __shared__ float As[8*128];
    __shared__ float Bs[8*128];
    const int i   = blockIdx.z;
    const int hm0 = blockIdx.y * 128;
    const int j0  = blockIdx.x * 128;
    const int tid = threadIdx.x;
    const int tx = tid & 15, ty = tid >> 4;
    const int lr = tid >> 1;
    const int lc = (tid & 1) * 4;

    float acc[8][8];
#pragma unroll
    for (int a = 0; a < 8; a++)
#pragma unroll
        for (int b = 0; b < 8; b++) acc[a][b] = 0.f;

    for (int k0 = 0; k0 < DHD; k0 += 8) {
        // A row m_ = hm; element = g_q[(hm)*L*DH + i*64 + k]
        float4 va = *(const float4*)(g_q + (size_t)(hm0 + lr)*(LL*DHD) + (size_t)i*DHD + k0 + lc);
        float4 vb = *(const float4*)(aK + ((size_t)i*LL + j0 + lr)*DHD + k0 + lc);
        __syncthreads();
        As[(lc+0)*128 + lr] = va.x; As[(lc+1)*128 + lr] = va.y;
        As[(lc+2)*128 + lr] = va.z; As[(lc+3)*128 + lr] = va.w;
        Bs[(lc+0)*128 + lr] = vb.x; Bs[(lc+1)*128 + lr] = vb.y;
        Bs[(lc+2)*128 + lr] = vb.z; Bs[(lc+3)*128 + lr] = vb.w;
        __syncthreads();
#pragma unroll
        for (int k = 0; k < 8; k++) {
            float a[8], b[8];
#pragma unroll
            for (int ii = 0; ii < 8; ii++) a[ii] = As[k*128 + ty + 16*ii];
#pragma unroll
            for (int jj = 0; jj < 8; jj++) b[jj] = Bs[k*128 + tx + 16*jj];
#pragma unroll
            for (int ii = 0; ii < 8; ii++)
#pragma unroll
                for (int jj = 0; jj < 8; jj++) acc[ii][jj] += a[ii]*b[jj];
        }
    }
#pragma unroll
    for (int ii = 0; ii < 8; ii++) {
#pragma unroll
        for (int jj = 0; jj < 8; jj++) {
            int hm = hm0 + ty + 16*ii;
            int j  = j0 + tx + 16*jj;
            g_e2[((size_t)hm*LL + i)*LL + j] = acc[ii][jj];
        }
    }
}

// ================= Fused attention ======================================================
// grid (itile=4, h=8, g=16); 256 threads; loops mm=0..3 (m = g*4+mm).
// Per m: S(64x256) = (q@k^T + E2)/8 -> softmax -> zacc += S@v ; Aacc += S.
// Writes g_zpart[g][h][itile] and g_apart[g][h][itile].
__global__ void attn_kernel() {
    extern __shared__ float sm[];
    float* qs   = sm;                         // 64x65  (transposed [d][i], pad 65)
    float* kb   = sm + 64*65;                 // 64x129 ([d][j] pad) / reused as vs 128x64
    float* S    = sm + 64*65 + 64*129;        // 64x257 ([i][j] pad 257)
    float* Aacc = S + 64*257;                 // 64x256

    const int i0  = blockIdx.x * 64;
    const int h   = blockIdx.y;
    const int g   = blockIdx.z;
    const int tid = threadIdx.x;
    const int tx = tid & 15, ty = tid >> 4;
    const int lane = tid & 31, w = tid >> 5;

    float zacc[4][4];
#pragma unroll
    for (int a = 0; a < 4; a++)
#pragma unroll
        for (int b = 0; b < 4; b++) zacc[a][b] = 0.f;

    for (int e = tid; e < 64*256; e += 256) Aacc[e] = 0.f;

    for (int mm = 0; mm < MPG; mm++) {
        const int m  = g*MPG + mm;
        const int hm = h*MSA + m;
        const float* qg = g_q + (size_t)hm*LL*DHD;
        const float* kg = g_k + (size_t)hm*LL*DHD;
        const float* vg = g_v + (size_t)hm*LL*DHD;
        const float* e2p = g_e2 + ((size_t)hm*LL + i0)*LL;

        __syncthreads();
        // load q tile transposed: qs[d][il]
        for (int e = tid; e < 64*64; e += 256) {
            int il = e >> 6, d = e & 63;
            qs[d*65 + il] = qg[(size_t)(i0 + il)*DHD + d];
        }
        // ---- S = (q k^T + E2)/8, two 128-col chunks, 4x8 micro ----
        for (int jc = 0; jc < 2; jc++) {
            __syncthreads();
            for (int e = tid; e < 128*64; e += 256) {
                int jl = e >> 6, d = e & 63;
                kb[d*129 + jl] = kg[(size_t)(jc*128 + jl)*DHD + d];
            }
            __syncthreads();
            float acc[4][8];
#pragma unroll
            for (int a = 0; a < 4; a++)
#pragma unroll
                for (int b = 0; b < 8; b++) acc[a][b] = 0.f;
#pragma unroll 16
            for (int d = 0; d < 64; d++) {
                float a[4], b[8];
#pragma unroll
                for (int ii = 0; ii < 4; ii++) a[ii] = qs[d*65 + ty + 16*ii];
#pragma unroll
                for (int jj = 0; jj < 8; jj++) b[jj] = kb[d*129 + tx + 16*jj];
#pragma unroll
                for (int ii = 0; ii < 4; ii++)
#pragma unroll
                    for (int jj = 0; jj < 8; jj++) acc[ii][jj] += a[ii]*b[jj];
            }
#pragma unroll
            for (int ii = 0; ii < 4; ii++) {
#pragma unroll
                for (int jj = 0; jj < 8; jj++) {
                    int il = ty + 16*ii;
                    int j  = jc*128 + tx + 16*jj;
                    S[il*257 + j] = (acc[ii][jj] + e2p[(size_t)il*LL + j]) * 0.125f;
                }
            }
        }
        __syncthreads();
        // ---- softmax: 8 warps, each handles rows w, w+8, ..., w+56 ----
        for (int rr = 0; rr < 8; rr++) {
            int r = w + 8*rr;
            float* Sr = S + r*257;
            float v[8];
            float mx = -1e30f;
#pragma unroll
            for (int c = 0; c < 8; c++) { v[c] = Sr[lane + 32*c]; mx = fmaxf(mx, v[c]); }
#pragma unroll
            for (int o = 16; o > 0; o >>= 1) mx = fmaxf(mx, __shfl_xor_sync(0xffffffffu, mx, o));
            float sum = 0.f;
#pragma unroll
            for (int c = 0; c < 8; c++) { v[c] = __expf(v[c] - mx); sum += v[c]; }
#pragma unroll
            for (int o = 16; o > 0; o >>= 1) sum += __shfl_xor_sync(0xffffffffu, sum, o);
            float inv = 1.f / sum;
#pragma unroll
            for (int c = 0; c < 8; c++) Sr[lane + 32*c] = v[c] * inv;
        }
        __syncthreads();
        // ---- Aacc += alpha ----
        for (int e = tid; e < 64*256; e += 256) {
            int il = e >> 8, j = e & 255;
            Aacc[e] += S[il*257 + j];
        }
        // ---- zacc += alpha @ v, two 128-j chunks, 4x4 micro ----
        for (int jc = 0; jc < 2; jc++) {
            __syncthreads();
            for (int e = tid; e < 128*64; e += 256)
                kb[e] = vg[(size_t)jc*128*DHD + e];       // vs[jl*64+d]
            __syncthreads();
#pragma unroll 8
            for (int jl = 0; jl < 128; jl++) {
                float a[4], b[4];
#pragma unroll
                for (int ii = 0; ii < 4; ii++) a[ii] = S[(ty + 16*ii)*257 + jc*128 + jl];
#pragma unroll
                for (int dd = 0; dd < 4; dd++) b[dd] = kb[jl*64 + tx + 16*dd];
#pragma unroll
                for (int ii = 0; ii < 4; ii++)
#pragma unroll
                    for (int dd = 0; dd < 4; dd++) zacc[ii][dd] += a[ii]*b[dd];
            }
        }
        __syncthreads();
    }
    // write partials
#pragma unroll
    for (int ii = 0; ii < 4; ii++)
#pragma unroll
        for (int dd = 0; dd < 4; dd++)
            g_zpart[(((size_t)g*HH + h)*LL + i0 + ty + 16*ii)*DHD + tx + 16*dd] = zacc[ii][dd];

    size_t abase = (((size_t)g*HH + h)*LL + i0)*LL;
    for (int e = tid; e < 64*256; e += 256) g_apart[abase + e] = Aacc[e];
}

// ================= Epilogue: reduce partials, z2 = A @ aV, write out =====================
// grid i = 256, 256 threads.
__global__ void final_kernel(const float* __restrict__ aV, float* __restrict__ out) {
    __shared__ float zs[512];      // [h*64+d]
    __shared__ float As[HH*LL];    // [h][j]
    const int i = blockIdx.x;
    const int tid = threadIdx.x;

    for (int p = tid; p < 512; p += 256) {
        int hq = p >> 6, d = p & 63;
        float s = 0.f;
#pragma unroll
        for (int g = 0; g < NG; g++)
            s += g_zpart[(((size_t)g*HH + hq)*LL + i)*DHD + d];
        zs[p] = s;
    }
    for (int p = tid; p < HH*LL; p += 256) {
        int hq = p >> 8, j = p & 255;
        float s = 0.f;
#pragma unroll
        for (int g = 0; g < NG; g++)
            s += g_apart[(((size_t)g*HH + hq)*LL + i)*LL + j];
        As[p] = s;
    }
    __syncthreads();

    const int d = tid & 63, hq2 = tid >> 6;   // hq2 in 0..3, handles heads 2*hq2, 2*hq2+1
    const float* av = aV + (size_t)i*LL*DHD;
    float a0 = 0.f, a1 = 0.f;
    for (int j = 0; j < LL; j++) {
        float vv = av[(size_t)j*DHD + d];
        a0 += As[(hq2*2 + 0)*LL + j] * vv;
        a1 += As[(hq2*2 + 1)*LL + j] * vv;
    }
    out[(size_t)i*DD + (hq2*2 + 0)*DHD + d] = zs[(hq2*2 + 0)*DHD + d] + a0;
    out[(size_t)i*DD + (hq2*2 + 1)*DHD + d] = zs[(hq2*2 + 1)*DHD + d] + a1;
}

// ================= launch ================================================================
extern "C" void kernel_launch(void* const* d_in, const int* in_sizes, int n_in,
                              void* d_out, int out_size) {
    const float* x  = (const float*)d_in[0];
    const float* Wq = (const float*)d_in[1];
    const float* Wk = (const float*)d_in[2];
    const float* Wv = (const float*)d_in[3];
    const float* aK = (const float*)d_in[4];
    const float* aV = (const float*)d_in[5];
    float* out = (float*)d_out;

    proj_kernel<<<dim3(4, 128, 3), 256>>>(x, Wq, Wk, Wv);
    e2_kernel<<<dim3(2, 4, 256), 256>>>(aK);

    const int attn_smem = (64*65 + 64*129 + 64*257 + 64*256) * (int)sizeof(float); // 180,992 B
    cudaFuncSetAttribute(attn_kernel, cudaFuncAttributeMaxDynamicSharedMemorySize, attn_smem);
    attn_kernel<<<dim3(4, 8, NG), 256, attn_smem>>>();

    final_kernel<<<256, 256>>>(aV, out);
}

// round 10
// speedup vs baseline: 1.2037x; 1.1961x over previous
#include <cuda_runtime.h>
#include <cstdint>

// Problem constants
#define HH   8
#define MSA  64
#define LL   256
#define DHD  64
#define DD   512
#define HMN  (HH*MSA)      // 512
#define NG   16            // m-groups
#define MPG  4             // m per group

// ---------------- device scratch (allocation-free rule: __device__ globals) -------------
__device__ float g_q[HMN*LL*DHD];
__device__ float g_k[HMN*LL*DHD];
__device__ float g_v[HMN*LL*DHD];
__device__ float g_e2[(size_t)HMN*LL*LL];
__device__ float g_zpart[NG*HH*LL*DHD];
__device__ float g_apart[(size_t)NG*HH*LL*LL];

// ======================= tf32 mma.sync helpers (baseline PTX, works on sm_103) ==========
__device__ __forceinline__ float tf32_rna(float v) {
    float r; asm("cvt.rna.tf32.f32 %0, %1;" : "=f"(r) : "f"(v)); return r;
}
__device__ __forceinline__ void split4(float4 v, float4& h, float4& l) {
    h.x = tf32_rna(v.x); h.y = tf32_rna(v.y); h.z = tf32_rna(v.z); h.w = tf32_rna(v.w);
    l.x = tf32_rna(v.x - h.x); l.y = tf32_rna(v.y - h.y);
    l.z = tf32_rna(v.z - h.z); l.w = tf32_rna(v.w - h.w);
}
// D(16x8) += A(16x8) * B(8x8);  A row-major frag (4 regs), B col-major frag (2 regs)
__device__ __forceinline__ void mma16n8k8(float* d, const float* a, const float* b) {
    asm volatile("mma.sync.aligned.m16n8k8.row.col.f32.tf32.tf32.f32 "
                 "{%0,%1,%2,%3}, {%4,%5,%6,%7}, {%8,%9}, {%0,%1,%2,%3};"
                 : "+f"(d[0]), "+f"(d[1]), "+f"(d[2]), "+f"(d[3])
                 : "r"(__float_as_uint(a[0])), "r"(__float_as_uint(a[1])),
                   "r"(__float_as_uint(a[2])), "r"(__float_as_uint(a[3])),
                   "r"(__float_as_uint(b[0])), "r"(__float_as_uint(b[1])));
}

#define TS 36                      // padded smem row stride (floats), conflict-free frags
#define TILE_SMEM (4*128*TS*4)     // Ah,Al,Bh,Bl : 73728 bytes

// Inner 128x128x32-chunk compute: warp tile 32x64 (2 x 8 m16n8k8 frags), 3-term tf32.
// Ah/Al: [128][TS] rows = M-tile rows, Bh/Bl: [128][TS] rows = N-tile rows.
__device__ __forceinline__ void tile_compute_chunk(
    const float* Ah, const float* Al, const float* Bh, const float* Bl,
    int wm, int wn, int gr, int gc, float dacc[2][8][4])
{
#pragma unroll
    for (int ks = 0; ks < 4; ks++) {
        const int k0 = ks * 8;
        float afh[2][4], afl[2][4];
#pragma unroll
        for (int i = 0; i < 2; i++) {
            const float* pa = &Ah[(wm + 16*i + gr)*TS + k0 + gc];
            afh[i][0] = pa[0]; afh[i][1] = pa[8*TS]; afh[i][2] = pa[4]; afh[i][3] = pa[8*TS+4];
            const float* pl = &Al[(wm + 16*i + gr)*TS + k0 + gc];
            afl[i][0] = pl[0]; afl[i][1] = pl[8*TS]; afl[i][2] = pl[4]; afl[i][3] = pl[8*TS+4];
        }
        float bfh[8][2], bfl[8][2];
#pragma unroll
        for (int j = 0; j < 8; j++) {
            const float* pb = &Bh[(wn + 8*j + gr)*TS + k0 + gc];
            bfh[j][0] = pb[0]; bfh[j][1] = pb[4];
            const float* pq = &Bl[(wn + 8*j + gr)*TS + k0 + gc];
            bfl[j][0] = pq[0]; bfl[j][1] = pq[4];
        }
#pragma unroll
        for (int i = 0; i < 2; i++)
#pragma unroll
            for (int j = 0; j < 8; j++) {
                mma16n8k8(dacc[i][j], afh[i], bfh[j]);
                mma16n8k8(dacc[i][j], afh[i], bfl[j]);
                mma16n8k8(dacc[i][j], afl[i], bfh[j]);
            }
    }
}

// ================= Projection via mma.sync tf32x3 ======================================
// C(16384x512) = X @ W^T, tile 128x128, K=512 in 16 chunks of 32.
// grid (ntile=4, mtile=128, w=3), 256 threads (8 warps, 4x2 warp grid).
__global__ __launch_bounds__(256, 1) void proj_tc_kernel(const float* __restrict__ x,
                                                         const float* __restrict__ Wq,
                                                         const float* __restrict__ Wk,
                                                         const float* __restrict__ Wv) {
    extern __shared__ float sm[];
    float* Ah = sm;
    float* Al = Ah + 128*TS;
    float* Bh = Al + 128*TS;
    float* Bl = Bh + 128*TS;

    const float* W; float* out;
    if (blockIdx.z == 0)      { W = Wq; out = g_q; }
    else if (blockIdx.z == 1) { W = Wk; out = g_k; }
    else                      { W = Wv; out = g_v; }

    const int row0 = blockIdx.y * 128;
    const int col0 = blockIdx.x * 128;
    const int tid  = threadIdx.x;
    const int wid  = tid >> 5, lane = tid & 31;
    const int wm = (wid & 3) * 32, wn = (wid >> 2) * 64;
    const int gr = lane >> 2, gc = lane & 3;

    float dacc[2][8][4];
#pragma unroll
    for (int i = 0; i < 2; i++)
#pragma unroll
        for (int j = 0; j < 8; j++)
#pragma unroll
            for (int c = 0; c < 4; c++) dacc[i][j][c] = 0.f;

    for (int kc = 0; kc < 16; kc++) {
        const int kb = kc * 32;
#pragma unroll
        for (int t = 0; t < 4; t++) {
            int idx = t * 256 + tid;
            int r  = idx >> 3;
            int kk = (idx & 7) << 2;
            float4 va = *(const float4*)(x + (size_t)(row0 + r) * DD + kb + kk);
            float4 vb = *(const float4*)(W + (size_t)(col0 + r) * DD + kb + kk);
            float4 ah, al, bh, bl;
            split4(va, ah, al);
            split4(vb, bh, bl);
            *(float4*)&Ah[r*TS + kk] = ah; *(float4*)&Al[r*TS + kk] = al;
            *(float4*)&Bh[r*TS + kk] = bh; *(float4*)&Bl[r*TS + kk] = bl;
        }
        __syncthreads();
        tile_compute_chunk(Ah, Al, Bh, Bl, wm, wn, gr, gc, dacc);
        __syncthreads();
    }

    // epilogue: scatter into (h,m,l,dh) layout, float2 stores (gcol even)
#pragma unroll
    for (int i = 0; i < 2; i++) {
#pragma unroll
        for (int j = 0; j < 8; j++) {
            int gcol = col0 + wn + 8*j + gc*2;
            int hq = gcol >> 6, dh = gcol & 63;
            int grow = row0 + wm + 16*i + gr;
            int ms = grow >> 8, l = grow & 255;
            *(float2*)&out[(((size_t)(hq*MSA + ms))*LL + l)*DHD + dh] =
                make_float2(dacc[i][j][0], dacc[i][j][1]);
            grow += 8; ms = grow >> 8; l = grow & 255;
            *(float2*)&out[(((size_t)(hq*MSA + ms))*LL + l)*DHD + dh] =
                make_float2(dacc[i][j][2], dacc[i][j][3]);
        }
    }
}

// ================= E2 via mma.sync tf32x3 ==============================================
// Per i: E2_i(512x256) = Qi(512x64) @ aK[i]^T. Tile 128x128, K=64 (2 chunks).
// grid (jt=2, hmt=4, i=256), 256 threads.
__global__ __launch_bounds__(256, 1) void e2_tc_kernel(const float* __restrict__ aK) {
    extern __shared__ float sm[];
    float* Ah = sm;
    float* Al = Ah + 128*TS;
    float* Bh = Al + 128*TS;
    float* Bl = Bh + 128*TS;

    const int i   = blockIdx.z;
    const int hm0 = blockIdx.y * 128;
    const int j0  = blockIdx.x * 128;
    const int tid = threadIdx.x;
    const int wid = tid >> 5, lane = tid & 31;
    const int wm = (wid & 3) * 32, wn = (wid >> 2) * 64;
    const int gr = lane >> 2, gc = lane & 3;

    float dacc[2][8][4];
#pragma unroll
    for (int a = 0; a < 2; a++)
#pragma unroll
        for (int b = 0; b < 8; b++)
#pragma unroll
            for (int c = 0; c < 4; c++) dacc[a][b][c] = 0.f;

    for (int kc = 0; kc < 2; kc++) {
        const int kb = kc * 32;
#pragma unroll
        for (int t = 0; t < 4; t++) {
            int idx = t * 256 + tid;
            int r  = idx >> 3;
            int kk = (idx & 7) << 2;
            float4 va = *(const float4*)(g_q + (size_t)(hm0 + r) * (LL*DHD) + (size_t)i * DHD + kb + kk);
            float4 vb = *(const float4*)(aK + ((size_t)i * LL + j0 + r) * DHD + kb + kk);
            float4 ah, al, bh, bl;
            split4(va, ah, al);
            split4(vb, bh, bl);
            *(float4*)&Ah[r*TS + kk] = ah; *(float4*)&Al[r*TS + kk] = al;
            *(float4*)&Bh[r*TS + kk] = bh; *(float4*)&Bl[r*TS + kk] = bl;
        }
        __syncthreads();
        tile_compute_chunk(Ah, Al, Bh, Bl, wm, wn, gr, gc, dacc);
        __syncthreads();
    }

#pragma unroll
    for (int a = 0; a < 2; a++) {
#pragma unroll
        for (int b = 0; b < 8; b++) {
            int jcol = j0 + wn + 8*b + gc*2;
            int hm = hm0 + wm + 16*a + gr;
            *(float2*)&g_e2[((size_t)hm*LL + i)*LL + jcol] =
                make_float2(dacc[a][b][0], dacc[a][b][1]);
            *(float2*)&g_e2[((size_t)(hm + 8)*LL + i)*LL + jcol] =
                make_float2(dacc[a][b][2], dacc[a][b][3]);
        }
    }
}

// ================= Fused attention (fp32, known-good) ==================================
__global__ void attn_kernel() {
    extern __shared__ float sm[];
    float* qs   = sm;                         // 64x65
    float* kb   = sm + 64*65;                 // 64x129 / reused as vs 128x64
    float* S    = sm + 64*65 + 64*129;        // 64x257
    float* Aacc = S + 64*257;                 // 64x256

    const int i0  = blockIdx.x * 64;
    const int h   = blockIdx.y;
    const int g   = blockIdx.z;
    const int tid = threadIdx.x;
    const int tx = tid & 15, ty = tid >> 4;
    const int lane = tid & 31, w = tid >> 5;

    float zacc[4][4];
#pragma unroll
    for (int a = 0; a < 4; a++)
#pragma unroll
        for (int b = 0; b < 4; b++) zacc[a][b] = 0.f;

    for (int e = tid; e < 64*256; e += 256) Aacc[e] = 0.f;

    for (int mm = 0; mm < MPG; mm++) {
        const int m  = g*MPG + mm;
        const int hm = h*MSA + m;
        const float* qg = g_q + (size_t)hm*LL*DHD;
        const float* kg = g_k + (size_t)hm*LL*DHD;
        const float* vg = g_v + (size_t)hm*LL*DHD;
        const float* e2p = g_e2 + ((size_t)hm*LL + i0)*LL;

        __syncthreads();
        for (int e = tid; e < 64*64; e += 256) {
            int il = e >> 6, d = e & 63;
            qs[d*65 + il] = qg[(size_t)(i0 + il)*DHD + d];
        }
        for (int jc = 0; jc < 2; jc++) {
            __syncthreads();
            for (int e = tid; e < 128*64; e += 256) {
                int jl = e >> 6, d = e & 63;
                kb[d*129 + jl] = kg[(size_t)(jc*128 + jl)*DHD + d];
            }
            __syncthreads();
            float acc[4][8];
#pragma unroll
            for (int a = 0; a < 4; a++)
#pragma unroll
                for (int b = 0; b < 8; b++) acc[a][b] = 0.f;
#pragma unroll 16
            for (int d = 0; d < 64; d++) {
                float a[4], b[8];
#pragma unroll
                for (int ii = 0; ii < 4; ii++) a[ii] = qs[d*65 + ty + 16*ii];
#pragma unroll
                for (int jj = 0; jj < 8; jj++) b[jj] = kb[d*129 + tx + 16*jj];
#pragma unroll
                for (int ii = 0; ii < 4; ii++)
#pragma unroll
                    for (int jj = 0; jj < 8; jj++) acc[ii][jj] += a[ii]*b[jj];
            }
#pragma unroll
            for (int ii = 0; ii < 4; ii++) {
#pragma unroll
                for (int jj = 0; jj < 8; jj++) {
                    int il = ty + 16*ii;
                    int j  = jc*128 + tx + 16*jj;
                    S[il*257 + j] = (acc[ii][jj] + e2p[(size_t)il*LL + j]) * 0.125f;
                }
            }
        }
        __syncthreads();
        for (int rr = 0; rr < 8; rr++) {
            int r = w + 8*rr;
            float* Sr = S + r*257;
            float v[8];
            float mx = -1e30f;
#pragma unroll
            for (int c = 0; c < 8; c++) { v[c] = Sr[lane + 32*c]; mx = fmaxf(mx, v[c]); }
#pragma unroll
            for (int o = 16; o > 0; o >>= 1) mx = fmaxf(mx, __shfl_xor_sync(0xffffffffu, mx, o));
            float sum = 0.f;
#pragma unroll
            for (int c = 0; c < 8; c++) { v[c] = __expf(v[c] - mx); sum += v[c]; }
#pragma unroll
            for (int o = 16; o > 0; o >>= 1) sum += __shfl_xor_sync(0xffffffffu, sum, o);
            float inv = 1.f / sum;
#pragma unroll
            for (int c = 0; c < 8; c++) Sr[lane + 32*c] = v[c] * inv;
        }
        __syncthreads();
        for (int e = tid; e < 64*256; e += 256) {
            int il = e >> 8, j = e & 255;
            Aacc[e] += S[il*257 + j];
        }
        for (int jc = 0; jc < 2; jc++) {
            __syncthreads();
            for (int e = tid; e < 128*64; e += 256)
                kb[e] = vg[(size_t)jc*128*DHD + e];
            __syncthreads();
#pragma unroll 8
            for (int jl = 0; jl < 128; jl++) {
                float a[4], b[4];
#pragma unroll
                for (int ii = 0; ii < 4; ii++) a[ii] = S[(ty + 16*ii)*257 + jc*128 + jl];
#pragma unroll
                for (int dd = 0; dd < 4; dd++) b[dd] = kb[jl*64 + tx + 16*dd];
#pragma unroll
                for (int ii = 0; ii < 4; ii++)
#pragma unroll
                    for (int dd = 0; dd < 4; dd++) zacc[ii][dd] += a[ii]*b[dd];
            }
        }
        __syncthreads();
    }
#pragma unroll
    for (int ii = 0; ii < 4; ii++)
#pragma unroll
        for (int dd = 0; dd < 4; dd++)
            g_zpart[(((size_t)g*HH + h)*LL + i0 + ty + 16*ii)*DHD + tx + 16*dd] = zacc[ii][dd];

    size_t abase = (((size_t)g*HH + h)*LL + i0)*LL;
    for (int e = tid; e < 64*256; e += 256) g_apart[abase + e] = Aacc[e];
}

// ================= Epilogue (unchanged) =================================================
__global__ void final_kernel(const float* __restrict__ aV, float* __restrict__ out) {
    __shared__ float zs[512];
    __shared__ float As[HH*LL];
    const int i = blockIdx.x;
    const int tid = threadIdx.x;

    for (int p = tid; p < 512; p += 256) {
        int hq = p >> 6, d = p & 63;
        float s = 0.f;
#pragma unroll
        for (int g = 0; g < NG; g++)
            s += g_zpart[(((size_t)g*HH + hq)*LL + i)*DHD + d];
        zs[p] = s;
    }
    for (int p = tid; p < HH*LL; p += 256) {
        int hq = p >> 8, j = p & 255;
        float s = 0.f;
#pragma unroll
        for (int g = 0; g < NG; g++)
            s += g_apart[(((size_t)g*HH + hq)*LL + i)*LL + j];
        As[p] = s;
    }
    __syncthreads();

    const int d = tid & 63, hq2 = tid >> 6;
    const float* av = aV + (size_t)i*LL*DHD;
    float a0 = 0.f, a1 = 0.f;
    for (int j = 0; j < LL; j++) {
        float vv = av[(size_t)j*DHD + d];
        a0 += As[(hq2*2 + 0)*LL + j] * vv;
        a1 += As[(hq2*2 + 1)*LL + j] * vv;
    }
    out[(size_t)i*DD + (hq2*2 + 0)*DHD + d] = zs[(hq2*2 + 0)*DHD + d] + a0;
    out[(size_t)i*DD + (hq2*2 + 1)*DHD + d] = zs[(hq2*2 + 1)*DHD + d] + a1;
}

// ================= launch ================================================================
extern "C" void kernel_launch(void* const* d_in, const int* in_sizes, int n_in,
                              void* d_out, int out_size) {
    const float* x  = (const float*)d_in[0];
    const float* Wq = (const float*)d_in[1];
    const float* Wk = (const float*)d_in[2];
    const float* Wv = (const float*)d_in[3];
    const float* aK = (const float*)d_in[4];
    const float* aV = (const float*)d_in[5];
    float* out = (float*)d_out;

    cudaFuncSetAttribute(proj_tc_kernel, cudaFuncAttributeMaxDynamicSharedMemorySize, TILE_SMEM);
    cudaFuncSetAttribute(e2_tc_kernel,   cudaFuncAttributeMaxDynamicSharedMemorySize, TILE_SMEM);

    proj_tc_kernel<<<dim3(4, 128, 3), 256, TILE_SMEM>>>(x, Wq, Wk, Wv);
    e2_tc_kernel<<<dim3(2, 4, 256), 256, TILE_SMEM>>>(aK);

    const int attn_smem = (64*65 + 64*129 + 64*257 + 64*256) * (int)sizeof(float);
    cudaFuncSetAttribute(attn_kernel, cudaFuncAttributeMaxDynamicSharedMemorySize, attn_smem);
    attn_kernel<<<dim3(4, 8, NG), 256, attn_smem>>>();

    final_kernel<<<256, 256>>>(aV, out);
}